// round 12
// baseline (speedup 1.0000x reference)
#include <cuda_runtime.h>
#include <cuda_fp16.h>
#include <cstdint>
#include <cstring>

// Fused MoE: cp.async fp32 stages -> smem convert -> fp16 ldmatrix + m16n8k16.
#define T_TOKENS 1024
#define DIM   1024
#define INTER 512
#define NEXP  16
#define TOPK  4
#define NROWS 5120
#define TMF   64
#define MAXT  96
#define STF   36        // fp32 stage row stride (u32 words)
#define STB   80        // fp16 buffer row stride (bytes)
#define P1GF  9216      // fp32 stage: gate array offset (bytes)
#define P1UF  18432     // fp32 stage: up array offset
#define P1SF  27648     // fp32 stage slot stride (also used in phase 2)
#define P1G   5120      // fp16 buffer: gate offset
#define P1U   10240     // fp16 buffer: up offset
#define P1S   15360     // fp16 buffer slot stride (both phases)
#define HSB   1040      // Hs row stride bytes
#define HSW   260       // Hs row stride u32

struct TileDesc { int e; int row0; int rows; };

__device__ int      g_counts[NEXP];
__device__ int      g_off[NEXP + 1];
__device__ int      g_idx[T_TOKENS * TOPK];
__device__ float    g_w[T_TOKENS * TOPK];
__device__ int      g_row_token[NROWS];
__device__ float    g_row_weight[NROWS];
__device__ TileDesc g_tiles[MAXT];
__device__ int      g_ntiles;

// ---- smem map: Hs | 4 fp32 stages | 2 fp16 buffers | meta ------------------
#define SM_HS    0            // 64 x 1040 = 66560
#define SM_F32   66560        // 4 x 27648 = 110592
#define SM_F16   177152       // 2 x 15360 = 30720
#define SM_RTOK  207872
#define SM_RWT   208128
#define SM_TOTAL 208384

__global__ void init_kernel() {
    if (threadIdx.x < NEXP) g_counts[threadIdx.x] = 0;
}

__global__ __launch_bounds__(256)
void gate_kernel(const float* __restrict__ x, const float* __restrict__ gw,
                 const float* __restrict__ gb) {
    const int token = (blockIdx.x * blockDim.x + threadIdx.x) >> 5;
    const int lane  = threadIdx.x & 31;
    if (token >= T_TOKENS) return;
    const float* xt = x + (size_t)token * DIM;
    float myscore = 0.f;
    for (int e = 0; e < NEXP; e++) {
        const float* we = gw + e * DIM;
        float p = 0.f;
        #pragma unroll 4
        for (int d = lane; d < DIM; d += 32) p += xt[d] * we[d];
        #pragma unroll
        for (int o = 16; o; o >>= 1) p += __shfl_xor_sync(0xffffffffu, p, o);
        if (lane == e) myscore = 1.0f / (1.0f + expf(-p));
    }
    float mybiased = (lane < NEXP) ? (myscore + gb[lane]) : -1e30f;
    float sum = 0.f; int kidx[TOPK]; float kw[TOPK];
    #pragma unroll
    for (int k = 0; k < TOPK; k++) {
        float v = mybiased; int bl = lane;
        #pragma unroll
        for (int o = 16; o; o >>= 1) {
            float ov = __shfl_xor_sync(0xffffffffu, v, o);
            int   ol = __shfl_xor_sync(0xffffffffu, bl, o);
            if (ov > v || (ov == v && ol < bl)) { v = ov; bl = ol; }
        }
        float sc = __shfl_sync(0xffffffffu, myscore, bl);
        kidx[k] = bl; kw[k] = sc; sum += sc;
        if (lane == bl) mybiased = -1e30f;
    }
    const float s = 2.5f / sum;
    if (lane == 0) {
        #pragma unroll
        for (int k = 0; k < TOPK; k++) {
            g_idx[token * TOPK + k] = kidx[k];
            g_w[token * TOPK + k]   = kw[k] * s;
            atomicAdd(&g_counts[kidx[k]], 1);
        }
        g_row_token[4096 + token]  = token;
        g_row_weight[4096 + token] = 1.0f;
    }
}

__global__ void sched_kernel() {
    int off = 0, nt = 0;
    for (int e = 0; e < NEXP; e++) {
        g_off[e] = off;
        int c = g_counts[e];
        for (int i = 0; i < c; i += TMF) {
            g_tiles[nt].e = e; g_tiles[nt].row0 = off + i;
            g_tiles[nt].rows = min(TMF, c - i); nt++;
        }
        off += c;
    }
    g_off[NEXP] = off;
    for (int i = 0; i < T_TOKENS; i += TMF) {
        g_tiles[nt].e = NEXP; g_tiles[nt].row0 = 4096 + i; g_tiles[nt].rows = TMF;
        nt++;
    }
    g_ntiles = nt;
}

__global__ void place_kernel() {
    __shared__ int s[T_TOKENS];
    int e = blockIdx.x, t = threadIdx.x;
    int myk = -1;
    #pragma unroll
    for (int k = 0; k < TOPK; k++)
        if (g_idx[t * TOPK + k] == e) myk = k;
    s[t] = (myk >= 0) ? 1 : 0;
    __syncthreads();
    for (int off = 1; off < T_TOKENS; off <<= 1) {
        int v = (t >= off) ? s[t - off] : 0;
        __syncthreads();
        s[t] += v;
        __syncthreads();
    }
    if (myk >= 0) {
        int row = g_off[e] + s[t] - 1;
        g_row_token[row]  = t;
        g_row_weight[row] = g_w[t * TOPK + myk];
    }
}

__device__ __forceinline__ uint32_t pk(float a, float b) {
    uint32_t r;
    asm("cvt.rn.f16x2.f32 %0, %1, %2;" : "=r"(r) : "f"(b), "f"(a));
    return r;   // lo=a hi=b
}
__device__ __forceinline__ void mma16(float* d, const uint32_t* a, const uint32_t* b) {
    asm volatile(
        "mma.sync.aligned.m16n8k16.row.col.f32.f16.f16.f32 "
        "{%0,%1,%2,%3},{%4,%5,%6,%7},{%8,%9},{%0,%1,%2,%3};"
        : "+f"(d[0]), "+f"(d[1]), "+f"(d[2]), "+f"(d[3])
        : "r"(a[0]), "r"(a[1]), "r"(a[2]), "r"(a[3]), "r"(b[0]), "r"(b[1]));
}
__device__ __forceinline__ void lx4(uint32_t* r, uint32_t a) {
    asm volatile("ldmatrix.sync.aligned.m8n8.x4.shared.b16 {%0,%1,%2,%3}, [%4];"
        : "=r"(r[0]), "=r"(r[1]), "=r"(r[2]), "=r"(r[3]) : "r"(a));
}
__device__ __forceinline__ void lx2(uint32_t* r, uint32_t a) {
    asm volatile("ldmatrix.sync.aligned.m8n8.x2.shared.b16 {%0,%1}, [%2];"
        : "=r"(r[0]), "=r"(r[1]) : "r"(a));
}
__device__ __forceinline__ void cp16(uint32_t d, const void* s) {
    asm volatile("cp.async.ca.shared.global [%0], [%1], 16;\n" :: "r"(d), "l"(s));
}
__device__ __forceinline__ void cp_commit() {
    asm volatile("cp.async.commit_group;\n");
}
__device__ __forceinline__ void cp_wait2() {
    asm volatile("cp.async.wait_group 2;\n");
}
__device__ __forceinline__ void cp_wait0() {
    asm volatile("cp.async.wait_group 0;\n");
}

__global__ __launch_bounds__(256, 1)
void fused_kernel(const float* __restrict__ x, const float* __restrict__ w13,
                  const float* __restrict__ w2, const float* __restrict__ w13_s,
                  const float* __restrict__ w2_s, float* __restrict__ out) {
    const int tile = blockIdx.x;
    if (tile >= g_ntiles) return;
    const TileDesc td = g_tiles[tile];
    const int row0 = td.row0, rows = td.rows;
    const float* B1 = (td.e < NEXP) ? (w13 + (size_t)td.e * 1024 * DIM) : w13_s;
    const float* B2 = (td.e < NEXP) ? (w2  + (size_t)td.e * DIM * INTER) : w2_s;

    extern __shared__ char smem[];
    uint32_t* Hs32 = (uint32_t*)smem;
    int*      rtok = (int*)(smem + SM_RTOK);
    float*    rwt  = (float*)(smem + SM_RWT);
    const uint32_t smA  = (uint32_t)__cvta_generic_to_shared(smem);
    const uint32_t hsA  = smA;
    const uint32_t f32A = smA + SM_F32;
    const uint32_t f16A = smA + SM_F16;

    const int tid = threadIdx.x, lane = tid & 31, warp = tid >> 5;
    const int wm = warp >> 2, wn = warp & 3;       // 2m x 4n
    const int g  = lane >> 2, tg = lane & 3;

    if (tid < TMF) {
        bool v = tid < rows;
        rtok[tid] = v ? g_row_token[row0 + tid] : 0;
        rwt[tid]  = v ? g_row_weight[row0 + tid] : 0.f;
    }
    __syncthreads();

    // ldmatrix lane addresses into fp16 buffers / Hs
    const uint32_t aLd  = f16A + (wm * 32 + (lane & 15)) * STB + (lane >> 4) * 16;
    const uint32_t bLd  = f16A + P1G + (wn * 16 + (lane & 7)) * STB + ((lane >> 3) & 1) * 16;
    const uint32_t hLd  = hsA + (wm * 32 + (lane & 15)) * HSB + (lane >> 4) * 16;
    const uint32_t b2Ld = f16A + (wn * 32 + (lane & 7)) * STB + ((lane >> 3) & 1) * 16;

    // ================= Phase 1: h = silu(x@Wg^T)*(x@Wu^T) -> Hs =============
    {
        const int r1 = tid & 63, s1 = tid >> 6;      // row, 8-float segment
        const float* aS = x + (size_t)rtok[r1] * DIM + s1 * 8;
        const float* gS = B1 + (size_t)r1 * DIM + s1 * 8;
        const float* uS = gS + (size_t)512 * DIM;
        const uint32_t f32d = f32A + (r1 * STF + s1 * 8) * 4;
        const int      cvF  = SM_F32 + (r1 * STF + s1 * 8) * 4;   // byte offsets
        const int      cvH  = SM_F16 + r1 * STB + s1 * 16;

#define CP1(stg, k, co) do { const uint32_t _d = f32d + (stg) * P1SF;          \
    const int _o = (k) * 32;                                                   \
    cp16(_d,            aS + _o);          cp16(_d + 16,          aS + _o + 4);\
    cp16(_d + P1GF,     gS + (co) + _o);   cp16(_d + P1GF + 16,   gS + (co) + _o + 4); \
    cp16(_d + P1UF,     uS + (co) + _o);   cp16(_d + P1UF + 16,   uS + (co) + _o + 4); } while (0)

#define CVT8(dst, src) do { float4 _v0 = *(const float4*)(smem + (src));       \
    float4 _v1 = *(const float4*)(smem + (src) + 16);                          \
    *(uint4*)(smem + (dst)) = make_uint4(pk(_v0.x,_v0.y), pk(_v0.z,_v0.w),     \
                                         pk(_v1.x,_v1.y), pk(_v1.z,_v1.w)); } while (0)
#define CONV1(stg, buf) do { const int _s = cvF + (stg) * P1SF;                \
    const int _h = cvH + (buf) * P1S;                                          \
    CVT8(_h,       _s);                                                        \
    CVT8(_h + P1G, _s + P1GF);                                                 \
    CVT8(_h + P1U, _s + P1UF); } while (0)

        for (int nc = 0; nc < 8; nc++) {
            const size_t co = (size_t)nc * 64 * DIM;
            float accG[2][2][4], accU[2][2][4];
            #pragma unroll
            for (int mi = 0; mi < 2; mi++)
                #pragma unroll
                for (int ni = 0; ni < 2; ni++)
                    #pragma unroll
                    for (int q = 0; q < 4; q++) { accG[mi][ni][q] = 0.f; accU[mi][ni][q] = 0.f; }

            __syncthreads();                         // stages + fp16 bufs free
            CP1(0, 0, co); cp_commit();
            CP1(1, 1, co); cp_commit();
            CP1(2, 2, co); cp_commit();
            cp_wait2();
            __syncthreads();                         // stage 0 visible
            CONV1(0, 0);

            #pragma unroll 1
            for (int it = 0; it < 32; it++) {
                if (it + 3 < 32) CP1((it + 3) & 3, it + 3, co);
                cp_commit();
                cp_wait2();
                __syncthreads();                     // stage it+1 visible; bufs settled
                if (it + 1 < 32) CONV1((it + 1) & 3, (it + 1) & 1);
                const uint32_t fb = (uint32_t)(it & 1) * P1S;
                #pragma unroll
                for (int ks = 0; ks < 2; ks++) {
                    const uint32_t ko = fb + ks * 32;
                    uint32_t af[2][4], bg[2][2], bu[2][2];
                    lx4(af[0], aLd + ko); lx4(af[1], aLd + ko + 16 * STB);
                    lx2(bg[0], bLd + ko); lx2(bg[1], bLd + ko + 8 * STB);
                    lx2(bu[0], bLd + (P1U - P1G) + ko);
                    lx2(bu[1], bLd + (P1U - P1G) + ko + 8 * STB);
                    #pragma unroll
                    for (int mi = 0; mi < 2; mi++)
                        #pragma unroll
                        for (int ni = 0; ni < 2; ni++) {
                            mma16(accG[mi][ni], af[mi], bg[ni]);
                            mma16(accU[mi][ni], af[mi], bu[ni]);
                        }
                }
            }
            // epilogue -> Hs fp16
            #pragma unroll
            for (int mi = 0; mi < 2; mi++) {
                const int r0 = wm * 32 + mi * 16 + g, r1e = r0 + 8;
                #pragma unroll
                for (int ni = 0; ni < 2; ni++) {
                    const int c = nc * 64 + wn * 16 + ni * 8 + 2 * tg;
                    float g0 = accG[mi][ni][0], g1 = accG[mi][ni][1];
                    float h0 = (g0 / (1.0f + expf(-g0))) * accU[mi][ni][0];
                    float h1 = (g1 / (1.0f + expf(-g1))) * accU[mi][ni][1];
                    Hs32[r0 * HSW + (c >> 1)] = pk(h0, h1);
                    float g2 = accG[mi][ni][2], g3 = accG[mi][ni][3];
                    float h2 = (g2 / (1.0f + expf(-g2))) * accU[mi][ni][2];
                    float h3 = (g3 / (1.0f + expf(-g3))) * accU[mi][ni][3];
                    Hs32[r1e * HSW + (c >> 1)] = pk(h2, h3);
                }
            }
        }
    }

    cp_wait0();
    __syncthreads();

    // ================= Phase 2: y = (h @ W2^T) * w -> atomicAdd =============
    {
        const int r2 = tid >> 1, s2 = tid & 1;       // row, 16-float segment
        const float* bS = B2 + (size_t)r2 * INTER + s2 * 16;
        const uint32_t f32d = f32A + (r2 * STF + s2 * 16) * 4;
        const int      cvF  = SM_F32 + (r2 * STF + s2 * 16) * 4;
        const int      cvH  = SM_F16 + r2 * STB + s2 * 32;

#define CP2(stg, k, co) do { const uint32_t _d = f32d + (stg) * P1SF;          \
    const float* _p = bS + (co) + (k) * 32;                                    \
    cp16(_d, _p); cp16(_d + 16, _p + 4); cp16(_d + 32, _p + 8); cp16(_d + 48, _p + 12); } while (0)
#define CONV2(stg, buf) do { const int _s = cvF + (stg) * P1SF;                \
    const int _h = cvH + (buf) * P1S;                                          \
    CVT8(_h, _s); CVT8(_h + 16, _s + 32); } while (0)

        for (int nb = 0; nb < 8; nb++) {
            const size_t co = (size_t)nb * 128 * INTER;
            float acc[2][4][4];
            #pragma unroll
            for (int mi = 0; mi < 2; mi++)
                #pragma unroll
                for (int ni = 0; ni < 4; ni++)
                    #pragma unroll
                    for (int q = 0; q < 4; q++) acc[mi][ni][q] = 0.f;

            __syncthreads();
            CP2(0, 0, co); cp_commit();
            CP2(1, 1, co); cp_commit();
            CP2(2, 2, co); cp_commit();
            cp_wait2();
            __syncthreads();
            CONV2(0, 0);

            #pragma unroll 1
            for (int it = 0; it < 16; it++) {
                if (it + 3 < 16) CP2((it + 3) & 3, it + 3, co);
                cp_commit();
                cp_wait2();
                __syncthreads();
                if (it + 1 < 16) CONV2((it + 1) & 3, (it + 1) & 1);
                const uint32_t fb = (uint32_t)(it & 1) * P1S;
                #pragma unroll
                for (int ks = 0; ks < 2; ks++) {
                    const uint32_t hko = (uint32_t)it * 64 + ks * 32;
                    uint32_t af[2][4], bf[4][2];
                    lx4(af[0], hLd + hko); lx4(af[1], hLd + hko + 16 * HSB);
                    #pragma unroll
                    for (int ni = 0; ni < 4; ni++)
                        lx2(bf[ni], b2Ld + fb + ni * 8 * STB + ks * 32);
                    #pragma unroll
                    for (int mi = 0; mi < 2; mi++)
                        #pragma unroll
                        for (int ni = 0; ni < 4; ni++)
                            mma16(acc[mi][ni], af[mi], bf[ni]);
                }
            }
            // epilogue: weighted atomics
            #pragma unroll
            for (int mi = 0; mi < 2; mi++) {
                const int r0 = wm * 32 + mi * 16 + g, r1e = r0 + 8;
                const float w0 = rwt[r0], w1 = rwt[r1e];
                const int   t0 = rtok[r0], t1 = rtok[r1e];
                #pragma unroll
                for (int ni = 0; ni < 4; ni++) {
                    const int col = nb * 128 + wn * 32 + ni * 8 + 2 * tg;
                    float* q0 = out + (size_t)t0 * DIM + col;
                    float* q1 = out + (size_t)t1 * DIM + col;
                    atomicAdd(q0 + 0, acc[mi][ni][0] * w0);
                    atomicAdd(q0 + 1, acc[mi][ni][1] * w0);
                    atomicAdd(q1 + 0, acc[mi][ni][2] * w1);
                    atomicAdd(q1 + 1, acc[mi][ni][3] * w1);
                }
            }
        }
    }
}

namespace {
struct EagerInit {
    EagerInit() {
        cudaFuncAttributes a;
        (void)cudaFuncGetAttributes(&a, (const void*)init_kernel);
        (void)cudaFuncGetAttributes(&a, (const void*)gate_kernel);
        (void)cudaFuncGetAttributes(&a, (const void*)sched_kernel);
        (void)cudaFuncGetAttributes(&a, (const void*)place_kernel);
        (void)cudaFuncGetAttributes(&a, (const void*)fused_kernel);
        (void)cudaFuncSetAttribute((const void*)fused_kernel,
                                   cudaFuncAttributeMaxDynamicSharedMemorySize, SM_TOTAL);
        int zeros[NEXP];
        memset(zeros, 0, sizeof(zeros));
        (void)cudaMemcpyToSymbol(g_counts, zeros, sizeof(zeros));
        init_kernel<<<1, 32>>>();
        (void)cudaDeviceSynchronize();
        (void)cudaGetLastError();
    }
};
static EagerInit eager_init_instance;
}  // namespace

extern "C" void kernel_launch(void* const* d_in, const int* in_sizes, int n_in,
                              void* d_out, int out_size) {
    const float* x     = (const float*)d_in[0];
    const float* gw    = (const float*)d_in[2];
    const float* gb    = (const float*)d_in[3];
    const float* w13   = (const float*)d_in[4];
    const float* w2    = (const float*)d_in[5];
    const float* w13_s = (const float*)d_in[6];
    const float* w2_s  = (const float*)d_in[7];
    float* out = (float*)d_out;

    (void)cudaFuncSetAttribute((const void*)fused_kernel,
                               cudaFuncAttributeMaxDynamicSharedMemorySize, SM_TOTAL);

    cudaMemsetAsync(out, 0, (size_t)out_size * sizeof(float), 0);
    init_kernel<<<1, 32>>>();
    gate_kernel<<<T_TOKENS / 8, 256>>>(x, gw, gb);
    sched_kernel<<<1, 1>>>();
    place_kernel<<<NEXP, T_TOKENS>>>();
    fused_kernel<<<MAXT, 256, SM_TOTAL>>>(x, w13, w2, w13_s, w2_s, out);
}

// round 13
// speedup vs baseline: 1.4415x; 1.4415x over previous
#include <cuda_runtime.h>
#include <cuda_bf16.h>
#include <cuda_fp16.h>
#include <cstdint>
#include <cstring>

// ---------------------------------------------------------------------------
// Fused MoE (R7 base + fp16-k16 phase-1 consumer).
//   fused per 64-row tile, 256 threads (8 warps = 2m x 4n):
//     Phase 1: GEMM1 (fp16 mma m16n8k16, frags packed from fp32 smem)
//              + silu*mul -> h tile (fp16) in SMEM
//     Phase 2: GEMM2 (fp16 mma m16n8k16) -> weighted atomicAdd into out
//   TK=32, depth-4 cp.async pipeline (wait_group 2 = 3 stages in flight).
// ---------------------------------------------------------------------------

#define T_TOKENS 1024
#define DIM      1024
#define INTER    512
#define NEXP     16
#define TOPK     4
#define NROWS    5120
#define TMF      64
#define MAXT     96
#define TK       32
#define TSTR     36              // stage row stride (uint32): 32 + 4 pad
#define HSTR2W   260             // Hs row stride in half2 words (520 halves)
#define NSTAGE   4
#define P1STAGE  27648           // bytes per phase-1 stage (3 x 64x36x4)
#define P1ARR    9216            // bytes per array within a stage
#define P2STAGE  18432           // bytes per phase-2 stage (128x36x4)

struct TileDesc { int e; int row0; int rows; };

__device__ int      g_counts[NEXP];
__device__ int      g_off[NEXP + 1];
__device__ int      g_idx[T_TOKENS * TOPK];
__device__ float    g_w[T_TOKENS * TOPK];
__device__ int      g_row_token[NROWS];
__device__ float    g_row_weight[NROWS];
__device__ TileDesc g_tiles[MAXT];
__device__ int      g_ntiles;

// ---- shared-memory layout --------------------------------------------------
#define SM_HS     0              // Hs[64][520] fp16 (h tile) = 66560 B
#define SM_ST     66560          // 4 stages: ph1 A/G/U | ph2 B
#define SM_RTOK   177152
#define SM_RWT    177408
#define SM_TOTAL  177664

// ---------------------------------------------------------------------------
__global__ void init_kernel() {
    if (threadIdx.x < NEXP) g_counts[threadIdx.x] = 0;
}

// ---------------------------------------------------------------------------
__global__ __launch_bounds__(256)
void gate_kernel(const float* __restrict__ x,
                 const float* __restrict__ gw,
                 const float* __restrict__ gb) {
    const int token = (blockIdx.x * blockDim.x + threadIdx.x) >> 5;
    const int lane  = threadIdx.x & 31;
    if (token >= T_TOKENS) return;
    const float* xt = x + (size_t)token * DIM;

    float myscore = 0.f;
    for (int e = 0; e < NEXP; e++) {
        const float* we = gw + e * DIM;
        float p = 0.f;
        #pragma unroll 4
        for (int d = lane; d < DIM; d += 32) p += xt[d] * we[d];
        #pragma unroll
        for (int o = 16; o; o >>= 1) p += __shfl_xor_sync(0xffffffffu, p, o);
        if (lane == e) myscore = 1.0f / (1.0f + expf(-p));
    }
    float mybiased = (lane < NEXP) ? (myscore + gb[lane]) : -1e30f;

    float sum = 0.f;
    int   kidx[TOPK]; float kw[TOPK];
    #pragma unroll
    for (int k = 0; k < TOPK; k++) {
        float v = mybiased; int bl = lane;
        #pragma unroll
        for (int o = 16; o; o >>= 1) {
            float ov = __shfl_xor_sync(0xffffffffu, v, o);
            int   ol = __shfl_xor_sync(0xffffffffu, bl, o);
            if (ov > v || (ov == v && ol < bl)) { v = ov; bl = ol; }
        }
        float sc = __shfl_sync(0xffffffffu, myscore, bl);
        kidx[k] = bl; kw[k] = sc; sum += sc;
        if (lane == bl) mybiased = -1e30f;
    }
    const float s = 2.5f / sum;
    if (lane == 0) {
        #pragma unroll
        for (int k = 0; k < TOPK; k++) {
            g_idx[token * TOPK + k] = kidx[k];
            g_w[token * TOPK + k]   = kw[k] * s;
            atomicAdd(&g_counts[kidx[k]], 1);
        }
        g_row_token[4096 + token]  = token;
        g_row_weight[4096 + token] = 1.0f;
    }
}

// ---------------------------------------------------------------------------
__global__ void sched_kernel() {
    int off = 0, nt = 0;
    for (int e = 0; e < NEXP; e++) {
        g_off[e] = off;
        int c = g_counts[e];
        for (int i = 0; i < c; i += TMF) {
            g_tiles[nt].e    = e;
            g_tiles[nt].row0 = off + i;
            g_tiles[nt].rows = min(TMF, c - i);
            nt++;
        }
        off += c;
    }
    g_off[NEXP] = off;
    for (int i = 0; i < T_TOKENS; i += TMF) {
        g_tiles[nt].e = NEXP; g_tiles[nt].row0 = 4096 + i; g_tiles[nt].rows = TMF;
        nt++;
    }
    g_ntiles = nt;
}

// ---------------------------------------------------------------------------
__global__ void place_kernel() {
    __shared__ int s[T_TOKENS];
    int e = blockIdx.x, t = threadIdx.x;
    int myk = -1;
    #pragma unroll
    for (int k = 0; k < TOPK; k++)
        if (g_idx[t * TOPK + k] == e) myk = k;
    s[t] = (myk >= 0) ? 1 : 0;
    __syncthreads();
    for (int off = 1; off < T_TOKENS; off <<= 1) {
        int v = (t >= off) ? s[t - off] : 0;
        __syncthreads();
        s[t] += v;
        __syncthreads();
    }
    if (myk >= 0) {
        int row = g_off[e] + s[t] - 1;
        g_row_token[row]  = t;
        g_row_weight[row] = g_w[t * TOPK + myk];
    }
}

// ---------------------------------------------------------------------------
__device__ __forceinline__ uint32_t pack_f16x2(float a, float b) {
    uint32_t r;
    asm("cvt.rn.f16x2.f32 %0, %1, %2;" : "=r"(r) : "f"(b), "f"(a));
    return r;   // lo=a hi=b
}
// load adjacent fp32 pair from smem, pack to fp16x2
__device__ __forceinline__ uint32_t lds_pk(const uint32_t* p) {
    float2 v = *(const float2*)p;
    return pack_f16x2(v.x, v.y);
}

__device__ __forceinline__ void mma_f16(float* d, const uint32_t* a, const uint32_t* b) {
    asm volatile(
        "mma.sync.aligned.m16n8k16.row.col.f32.f16.f16.f32 "
        "{%0,%1,%2,%3},{%4,%5,%6,%7},{%8,%9},{%0,%1,%2,%3};"
        : "+f"(d[0]), "+f"(d[1]), "+f"(d[2]), "+f"(d[3])
        : "r"(a[0]), "r"(a[1]), "r"(a[2]), "r"(a[3]), "r"(b[0]), "r"(b[1]));
}

__device__ __forceinline__ void cp16(uint32_t smem_dst, const void* gsrc) {
    asm volatile("cp.async.ca.shared.global [%0], [%1], 16;\n"
                 :: "r"(smem_dst), "l"(gsrc));
}
__device__ __forceinline__ void cp_commit() {
    asm volatile("cp.async.commit_group;\n");
}
__device__ __forceinline__ void cp_wait2() {
    asm volatile("cp.async.wait_group 2;\n");
}

// ---------------------------------------------------------------------------
// Fused expert kernel: one 64-row tile per block, 256 threads (8 warps).
__global__ __launch_bounds__(256)
void fused_kernel(const float* __restrict__ x,
                  const float* __restrict__ w13,
                  const float* __restrict__ w2,
                  const float* __restrict__ w13_s,
                  const float* __restrict__ w2_s,
                  float* __restrict__ out) {
    const int tile = blockIdx.x;
    if (tile >= g_ntiles) return;
    const TileDesc td = g_tiles[tile];
    const int row0 = td.row0, rows = td.rows;
    const float* B1 = (td.e < NEXP) ? (w13 + (size_t)td.e * 1024 * DIM) : w13_s;
    const float* B2 = (td.e < NEXP) ? (w2  + (size_t)td.e * DIM * INTER) : w2_s;

    extern __shared__ char smem[];
    uint32_t* Hs   = (uint32_t*)(smem + SM_HS);     // [64][HSTR2W] half2 words
    char*     ST   = smem + SM_ST;
    int*      rtok = (int*)(smem + SM_RTOK);
    float*    rwt  = (float*)(smem + SM_RWT);

    const int tid  = threadIdx.x;
    const int lane = tid & 31, warp = tid >> 5;
    const int wm = warp >> 2, wn = warp & 3;        // 2 (m) x 4 (n)
    const int g  = lane >> 2, tg = lane & 3;

    if (tid < TMF) {
        bool v = tid < rows;
        rtok[tid] = v ? g_row_token[row0 + tid] : 0;
        rwt[tid]  = v ? g_row_weight[row0 + tid] : 0.f;
    }
    __syncthreads();

    const uint32_t stBase = (uint32_t)__cvta_generic_to_shared(ST);

    // phase-1 loader slots: 512 slots (64 rows x 8 16B-chunks), 2 per thread
    const int r1a = tid >> 3,         c1a = (tid & 7) * 4;
    const int r1b = (tid + 256) >> 3, c1b = ((tid + 256) & 7) * 4;
    const float* aSrcA = x + (size_t)rtok[r1a] * DIM + c1a;
    const float* aSrcB = x + (size_t)rtok[r1b] * DIM + c1b;
    const uint32_t dA_a = stBase + (r1a * TSTR + c1a) * 4;
    const uint32_t dA_b = stBase + (r1b * TSTR + c1b) * 4;

    // ======================= Phase 1: h = silu(x@Wg^T) * (x@Wu^T) ==========
    for (int nc = 0; nc < 8; nc++) {                 // 64-col chunks of gate/up
        float accG[2][2][4], accU[2][2][4];
        #pragma unroll
        for (int mi = 0; mi < 2; mi++)
            #pragma unroll
            for (int ni = 0; ni < 2; ni++)
                #pragma unroll
                for (int q = 0; q < 4; q++) { accG[mi][ni][q] = 0.f; accU[mi][ni][q] = 0.f; }

        const float* gSrcA = B1 + (size_t)(nc * 64 + r1a) * DIM + c1a;
        const float* gSrcB = B1 + (size_t)(nc * 64 + r1b) * DIM + c1b;
        const float* uSrcA = gSrcA + (size_t)512 * DIM;
        const float* uSrcB = gSrcB + (size_t)512 * DIM;

        __syncthreads();            // previous chunk done with stage buffers
        #pragma unroll
        for (int s = 0; s < NSTAGE - 1; s++) {       // prologue
            const int off = s * TK;
            const uint32_t sb = s * P1STAGE;
            cp16(dA_a + sb, aSrcA + off);            cp16(dA_b + sb, aSrcB + off);
            cp16(dA_a + sb + P1ARR, gSrcA + off);    cp16(dA_b + sb + P1ARR, gSrcB + off);
            cp16(dA_a + sb + 2*P1ARR, uSrcA + off);  cp16(dA_b + sb + 2*P1ARR, uSrcB + off);
            cp_commit();
        }

        #pragma unroll 1
        for (int it = 0; it < DIM / TK; it++) {      // 32 iterations
            cp_wait2();
            __syncthreads();
            if (it + NSTAGE - 1 < DIM / TK) {
                const int off = (it + NSTAGE - 1) * TK;
                const uint32_t sb = ((it + NSTAGE - 1) & 3) * P1STAGE;
                cp16(dA_a + sb, aSrcA + off);            cp16(dA_b + sb, aSrcB + off);
                cp16(dA_a + sb + P1ARR, gSrcA + off);    cp16(dA_b + sb + P1ARR, gSrcB + off);
                cp16(dA_a + sb + 2*P1ARR, uSrcA + off);  cp16(dA_b + sb + 2*P1ARR, uSrcB + off);
            }
            cp_commit();
            const uint32_t* AsP = (const uint32_t*)(ST + (it & 3) * P1STAGE);
            const uint32_t* BgP = (const uint32_t*)(ST + (it & 3) * P1STAGE + P1ARR);
            const uint32_t* BuP = (const uint32_t*)(ST + (it & 3) * P1STAGE + 2 * P1ARR);
            // fp16 m16n8k16 consumer: frags = LDS.64 pair + pack
            #pragma unroll
            for (int ks = 0; ks < 2; ks++) {
                const int kk = ks * 16;
                uint32_t af[2][4], bg[2][2], bu[2][2];
                #pragma unroll
                for (int mi = 0; mi < 2; mi++) {
                    const int r = wm * 32 + mi * 16;
                    af[mi][0] = lds_pk(&AsP[(r + g    ) * TSTR + kk + 2 * tg]);
                    af[mi][1] = lds_pk(&AsP[(r + g + 8) * TSTR + kk + 2 * tg]);
                    af[mi][2] = lds_pk(&AsP[(r + g    ) * TSTR + kk + 8 + 2 * tg]);
                    af[mi][3] = lds_pk(&AsP[(r + g + 8) * TSTR + kk + 8 + 2 * tg]);
                }
                #pragma unroll
                for (int ni = 0; ni < 2; ni++) {
                    const int c = wn * 16 + ni * 8 + g;
                    bg[ni][0] = lds_pk(&BgP[c * TSTR + kk + 2 * tg]);
                    bg[ni][1] = lds_pk(&BgP[c * TSTR + kk + 8 + 2 * tg]);
                    bu[ni][0] = lds_pk(&BuP[c * TSTR + kk + 2 * tg]);
                    bu[ni][1] = lds_pk(&BuP[c * TSTR + kk + 8 + 2 * tg]);
                }
                #pragma unroll
                for (int mi = 0; mi < 2; mi++)
                    #pragma unroll
                    for (int ni = 0; ni < 2; ni++) {
                        mma_f16(accG[mi][ni], af[mi], bg[ni]);
                        mma_f16(accU[mi][ni], af[mi], bu[ni]);
                    }
            }
        }

        // epilogue: h = silu(g)*u -> Hs as packed fp16 pairs
        #pragma unroll
        for (int mi = 0; mi < 2; mi++) {
            int r0 = wm * 32 + mi * 16 + g;
            int r1 = r0 + 8;
            #pragma unroll
            for (int ni = 0; ni < 2; ni++) {
                int c = nc * 64 + wn * 16 + ni * 8 + 2 * tg;   // even
                float g0 = accG[mi][ni][0], g1 = accG[mi][ni][1];
                float h0 = (g0 / (1.0f + expf(-g0))) * accU[mi][ni][0];
                float h1 = (g1 / (1.0f + expf(-g1))) * accU[mi][ni][1];
                Hs[r0 * HSTR2W + (c >> 1)] = pack_f16x2(h0, h1);
                float g2 = accG[mi][ni][2], g3 = accG[mi][ni][3];
                float h2 = (g2 / (1.0f + expf(-g2))) * accU[mi][ni][2];
                float h3 = (g3 / (1.0f + expf(-g3))) * accU[mi][ni][3];
                Hs[r1 * HSTR2W + (c >> 1)] = pack_f16x2(h2, h3);
            }
        }
    }

    // ======================= Phase 2: y = (h @ W2^T) * rowwt ===============
    // loader: 1024 slots (128 rows x 8 chunks), 4 per thread
    const int r2[4] = { tid >> 3, (tid + 256) >> 3, (tid + 512) >> 3, (tid + 768) >> 3 };
    const int c2[4] = { (tid & 7) * 4, ((tid + 256) & 7) * 4,
                        ((tid + 512) & 7) * 4, ((tid + 768) & 7) * 4 };

    for (int nb = 0; nb < 8; nb++) {                 // 128-col chunks of DIM
        const int n0 = nb * 128;
        float acc[2][4][4];
        #pragma unroll
        for (int mi = 0; mi < 2; mi++)
            #pragma unroll
            for (int ni = 0; ni < 4; ni++)
                #pragma unroll
                for (int q = 0; q < 4; q++) acc[mi][ni][q] = 0.f;

        const float* bSrc[4];
        uint32_t dB[4];
        #pragma unroll
        for (int i = 0; i < 4; i++) {
            bSrc[i] = B2 + (size_t)(n0 + r2[i]) * INTER + c2[i];
            dB[i]   = stBase + (r2[i] * TSTR + c2[i]) * 4;
        }

        __syncthreads();
        #pragma unroll
        for (int s = 0; s < NSTAGE - 1; s++) {
            const int off = s * TK;
            const uint32_t sb = s * P2STAGE;
            #pragma unroll
            for (int i = 0; i < 4; i++) cp16(dB[i] + sb, bSrc[i] + off);
            cp_commit();
        }

        #pragma unroll 1
        for (int it = 0; it < INTER / TK; it++) {    // 16 iterations
            cp_wait2();
            __syncthreads();
            if (it + NSTAGE - 1 < INTER / TK) {
                const int off = (it + NSTAGE - 1) * TK;
                const uint32_t sb = ((it + NSTAGE - 1) & 3) * P2STAGE;
                #pragma unroll
                for (int i = 0; i < 4; i++) cp16(dB[i] + sb, bSrc[i] + off);
            }
            cp_commit();
            const uint32_t* BsP = (const uint32_t*)(ST + (it & 3) * P2STAGE);
            const int kt = it * TK;
            #pragma unroll
            for (int ks = 0; ks < 2; ks++) {         // two k16 sub-steps
                const int kk = ks * 16;
                uint32_t af[2][4], bf[4][2];
                #pragma unroll
                for (int mi = 0; mi < 2; mi++) {
                    const int r = wm * 32 + mi * 16;
                    const int h0 = (kt + kk) >> 1;   // half2 word index base
                    af[mi][0] = Hs[(r + g    ) * HSTR2W + h0 + tg];
                    af[mi][1] = Hs[(r + g + 8) * HSTR2W + h0 + tg];
                    af[mi][2] = Hs[(r + g    ) * HSTR2W + h0 + 4 + tg];
                    af[mi][3] = Hs[(r + g + 8) * HSTR2W + h0 + 4 + tg];
                }
                #pragma unroll
                for (int ni = 0; ni < 4; ni++) {
                    const int c = wn * 32 + ni * 8 + g;
                    bf[ni][0] = lds_pk(&BsP[c * TSTR + kk + 2 * tg]);
                    bf[ni][1] = lds_pk(&BsP[c * TSTR + kk + 8 + 2 * tg]);
                }
                #pragma unroll
                for (int mi = 0; mi < 2; mi++)
                    #pragma unroll
                    for (int ni = 0; ni < 4; ni++)
                        mma_f16(acc[mi][ni], af[mi], bf[ni]);
            }
        }

        // epilogue: weighted atomic accumulate into out
        #pragma unroll
        for (int mi = 0; mi < 2; mi++) {
            int r0 = wm * 32 + mi * 16 + g;
            int r1 = r0 + 8;
            float w0 = rwt[r0], w1 = rwt[r1];
            int   t0 = rtok[r0], t1 = rtok[r1];
            #pragma unroll
            for (int ni = 0; ni < 4; ni++) {
                int col = n0 + wn * 32 + ni * 8 + 2 * tg;
                float* q0 = out + (size_t)t0 * DIM + col;
                float* q1 = out + (size_t)t1 * DIM + col;
                atomicAdd(q0 + 0, acc[mi][ni][0] * w0);
                atomicAdd(q0 + 1, acc[mi][ni][1] * w0);
                atomicAdd(q1 + 0, acc[mi][ni][2] * w1);
                atomicAdd(q1 + 1, acc[mi][ni][3] * w1);
            }
        }
    }
}

// ---------------------------------------------------------------------------
namespace {
struct EagerInit {
    EagerInit() {
        cudaFuncAttributes a;
        (void)cudaFuncGetAttributes(&a, (const void*)init_kernel);
        (void)cudaFuncGetAttributes(&a, (const void*)gate_kernel);
        (void)cudaFuncGetAttributes(&a, (const void*)sched_kernel);
        (void)cudaFuncGetAttributes(&a, (const void*)place_kernel);
        (void)cudaFuncGetAttributes(&a, (const void*)fused_kernel);
        (void)cudaFuncSetAttribute((const void*)fused_kernel,
                                   cudaFuncAttributeMaxDynamicSharedMemorySize, SM_TOTAL);
        int zeros[NEXP];
        memset(zeros, 0, sizeof(zeros));
        (void)cudaMemcpyToSymbol(g_counts, zeros, sizeof(zeros));
        init_kernel<<<1, 32>>>();
        (void)cudaDeviceSynchronize();
        (void)cudaGetLastError();
    }
};
static EagerInit eager_init_instance;
}  // namespace

// ---------------------------------------------------------------------------
extern "C" void kernel_launch(void* const* d_in, const int* in_sizes, int n_in,
                              void* d_out, int out_size) {
    const float* x     = (const float*)d_in[0];
    const float* gw    = (const float*)d_in[2];
    const float* gb    = (const float*)d_in[3];
    const float* w13   = (const float*)d_in[4];
    const float* w2    = (const float*)d_in[5];
    const float* w13_s = (const float*)d_in[6];
    const float* w2_s  = (const float*)d_in[7];
    float* out = (float*)d_out;

    (void)cudaFuncSetAttribute((const void*)fused_kernel,
                               cudaFuncAttributeMaxDynamicSharedMemorySize, SM_TOTAL);

    cudaMemsetAsync(out, 0, (size_t)out_size * sizeof(float), 0);
    init_kernel<<<1, 32>>>();
    gate_kernel<<<T_TOKENS / 8, 256>>>(x, gw, gb);
    sched_kernel<<<1, 1>>>();
    place_kernel<<<NEXP, T_TOKENS>>>();
    fused_kernel<<<MAXT, 256, SM_TOTAL>>>(x, w13, w2, w13_s, w2_s, out);
}

// round 15
// speedup vs baseline: 2.0549x; 1.4255x over previous
#include <cuda_runtime.h>
#include <cuda_fp16.h>
#include <cstdint>
#include <cstring>

// ---------------------------------------------------------------------------
// MoE, two-GEMM split with h in a small fp16 device buffer.
//   K1: per (64-row tile, 64-col chunk): h = silu(x@Wg^T)*(x@Wu^T) -> g_h fp16
//   K2: per (64-row tile, 128-col chunk): y = (h@W2^T)*w -> atomicAdd out
// Both: cp.async depth-4 fp32 stages (R7 pipeline), fp16 m16n8k16 consumers
// (R13). 2 blocks/SM, ~768-block grids -> cross-block latency hiding.
// ---------------------------------------------------------------------------

#define T_TOKENS 1024
#define DIM      1024
#define INTER    512
#define NEXP     16
#define TOPK     4
#define NROWS    5120
#define TMF      64
#define MAXT     96
#define TK       32
#define TSTR     36              // fp32 stage row stride (u32): 32 + 4 pad
#define NSTAGE   4
// K1 stage: A + G + U, each 64 x TSTR x 4 B
#define P1ARR    9216
#define P1STAGE  27648
// K2 stage: Ah (fp16 64 x 20 u32) + B (fp32 128 x TSTR x 4)
#define A2STR    20              // fp16 A row stride in u32 (40 halves)
#define A2SZ     5120
#define B2OFF    5120
#define P2STAGE  23552

struct TileDesc { int e; int row0; int rows; };

__device__ int      g_counts[NEXP];
__device__ int      g_off[NEXP + 1];
__device__ int      g_idx[T_TOKENS * TOPK];
__device__ float    g_w[T_TOKENS * TOPK];
__device__ int      g_row_token[NROWS];
__device__ float    g_row_weight[NROWS];
__device__ TileDesc g_tiles[MAXT];
__device__ int      g_ntiles;
__device__ __half   g_h[(size_t)NROWS * INTER];   // 5.24 MB intermediate

// ---- smem layouts ----------------------------------------------------------
#define SM1_ST    0
#define SM1_RTOK  110592
#define SM1_RWT   110848
#define SM1_TOTAL 111104         // <= 113.6KB -> 2 blocks/SM

#define SM2_ST    0
#define SM2_RTOK  94208
#define SM2_RWT   94464
#define SM2_TOTAL 94720          // 2 blocks/SM

// ---------------------------------------------------------------------------
__global__ void init_kernel() {
    if (threadIdx.x < NEXP) g_counts[threadIdx.x] = 0;
}

__global__ __launch_bounds__(256)
void gate_kernel(const float* __restrict__ x, const float* __restrict__ gw,
                 const float* __restrict__ gb) {
    const int token = (blockIdx.x * blockDim.x + threadIdx.x) >> 5;
    const int lane  = threadIdx.x & 31;
    if (token >= T_TOKENS) return;
    const float* xt = x + (size_t)token * DIM;
    float myscore = 0.f;
    for (int e = 0; e < NEXP; e++) {
        const float* we = gw + e * DIM;
        float p = 0.f;
        #pragma unroll 4
        for (int d = lane; d < DIM; d += 32) p += xt[d] * we[d];
        #pragma unroll
        for (int o = 16; o; o >>= 1) p += __shfl_xor_sync(0xffffffffu, p, o);
        if (lane == e) myscore = 1.0f / (1.0f + expf(-p));
    }
    float mybiased = (lane < NEXP) ? (myscore + gb[lane]) : -1e30f;
    float sum = 0.f; int kidx[TOPK]; float kw[TOPK];
    #pragma unroll
    for (int k = 0; k < TOPK; k++) {
        float v = mybiased; int bl = lane;
        #pragma unroll
        for (int o = 16; o; o >>= 1) {
            float ov = __shfl_xor_sync(0xffffffffu, v, o);
            int   ol = __shfl_xor_sync(0xffffffffu, bl, o);
            if (ov > v || (ov == v && ol < bl)) { v = ov; bl = ol; }
        }
        float sc = __shfl_sync(0xffffffffu, myscore, bl);
        kidx[k] = bl; kw[k] = sc; sum += sc;
        if (lane == bl) mybiased = -1e30f;
    }
    const float s = 2.5f / sum;
    if (lane == 0) {
        #pragma unroll
        for (int k = 0; k < TOPK; k++) {
            g_idx[token * TOPK + k] = kidx[k];
            g_w[token * TOPK + k]   = kw[k] * s;
            atomicAdd(&g_counts[kidx[k]], 1);
        }
        g_row_token[4096 + token]  = token;
        g_row_weight[4096 + token] = 1.0f;
    }
}

__global__ void sched_kernel() {
    int off = 0, nt = 0;
    for (int e = 0; e < NEXP; e++) {
        g_off[e] = off;
        int c = g_counts[e];
        for (int i = 0; i < c; i += TMF) {
            g_tiles[nt].e = e; g_tiles[nt].row0 = off + i;
            g_tiles[nt].rows = min(TMF, c - i); nt++;
        }
        off += c;
    }
    g_off[NEXP] = off;
    for (int i = 0; i < T_TOKENS; i += TMF) {
        g_tiles[nt].e = NEXP; g_tiles[nt].row0 = 4096 + i; g_tiles[nt].rows = TMF;
        nt++;
    }
    g_ntiles = nt;
}

__global__ void place_kernel() {
    __shared__ int s[T_TOKENS];
    int e = blockIdx.x, t = threadIdx.x;
    int myk = -1;
    #pragma unroll
    for (int k = 0; k < TOPK; k++)
        if (g_idx[t * TOPK + k] == e) myk = k;
    s[t] = (myk >= 0) ? 1 : 0;
    __syncthreads();
    for (int off = 1; off < T_TOKENS; off <<= 1) {
        int v = (t >= off) ? s[t - off] : 0;
        __syncthreads();
        s[t] += v;
        __syncthreads();
    }
    if (myk >= 0) {
        int row = g_off[e] + s[t] - 1;
        g_row_token[row]  = t;
        g_row_weight[row] = g_w[t * TOPK + myk];
    }
}

// ---------------------------------------------------------------------------
__device__ __forceinline__ uint32_t pack_f16x2(float a, float b) {
    uint32_t r;
    asm("cvt.rn.f16x2.f32 %0, %1, %2;" : "=r"(r) : "f"(b), "f"(a));
    return r;   // lo=a hi=b
}
__device__ __forceinline__ uint32_t lds_pk(const uint32_t* p) {
    float2 v = *(const float2*)p;
    return pack_f16x2(v.x, v.y);
}
__device__ __forceinline__ void mma_f16(float* d, const uint32_t* a, const uint32_t* b) {
    asm volatile(
        "mma.sync.aligned.m16n8k16.row.col.f32.f16.f16.f32 "
        "{%0,%1,%2,%3},{%4,%5,%6,%7},{%8,%9},{%0,%1,%2,%3};"
        : "+f"(d[0]), "+f"(d[1]), "+f"(d[2]), "+f"(d[3])
        : "r"(a[0]), "r"(a[1]), "r"(a[2]), "r"(a[3]), "r"(b[0]), "r"(b[1]));
}
__device__ __forceinline__ void cp16(uint32_t smem_dst, const void* gsrc) {
    asm volatile("cp.async.ca.shared.global [%0], [%1], 16;\n"
                 :: "r"(smem_dst), "l"(gsrc));
}
__device__ __forceinline__ void cp_commit() {
    asm volatile("cp.async.commit_group;\n");
}
__device__ __forceinline__ void cp_wait2() {
    asm volatile("cp.async.wait_group 2;\n");
}

// ---------------------------------------------------------------------------
// K1: h[row0..row0+63][nc*64..+64) = silu(x@Wg^T) * (x@Wu^T)  (fp16)
// grid (MAXT, 8), 256 threads (2m x 4n warps), R7/R13-proven inner loop.
__global__ __launch_bounds__(256, 2)
void gemm1_kernel(const float* __restrict__ x, const float* __restrict__ w13,
                  const float* __restrict__ w13_s) {
    const int tile = blockIdx.x;
    if (tile >= g_ntiles) return;
    const TileDesc td = g_tiles[tile];
    const int row0 = td.row0, rows = td.rows;
    const int nc = blockIdx.y;
    const float* B1 = (td.e < NEXP) ? (w13 + (size_t)td.e * 1024 * DIM) : w13_s;

    extern __shared__ char smem[];
    char* ST   = smem + SM1_ST;
    int*  rtok = (int*)(smem + SM1_RTOK);

    const int tid = threadIdx.x, lane = tid & 31, warp = tid >> 5;
    const int wm = warp >> 2, wn = warp & 3;
    const int g  = lane >> 2, tg = lane & 3;

    if (tid < TMF)
        rtok[tid] = (tid < rows) ? g_row_token[row0 + tid] : 0;
    __syncthreads();

    const uint32_t stBase = (uint32_t)__cvta_generic_to_shared(ST);
    const int r1a = tid >> 3,         c1a = (tid & 7) * 4;
    const int r1b = (tid + 256) >> 3, c1b = ((tid + 256) & 7) * 4;
    const float* aSrcA = x + (size_t)rtok[r1a] * DIM + c1a;
    const float* aSrcB = x + (size_t)rtok[r1b] * DIM + c1b;
    const uint32_t dA_a = stBase + (r1a * TSTR + c1a) * 4;
    const uint32_t dA_b = stBase + (r1b * TSTR + c1b) * 4;
    const float* gSrcA = B1 + (size_t)(nc * 64 + r1a) * DIM + c1a;
    const float* gSrcB = B1 + (size_t)(nc * 64 + r1b) * DIM + c1b;
    const float* uSrcA = gSrcA + (size_t)512 * DIM;
    const float* uSrcB = gSrcB + (size_t)512 * DIM;

    float accG[2][2][4], accU[2][2][4];
    #pragma unroll
    for (int mi = 0; mi < 2; mi++)
        #pragma unroll
        for (int ni = 0; ni < 2; ni++)
            #pragma unroll
            for (int q = 0; q < 4; q++) { accG[mi][ni][q] = 0.f; accU[mi][ni][q] = 0.f; }

    #pragma unroll
    for (int s = 0; s < NSTAGE - 1; s++) {
        const int off = s * TK;
        const uint32_t sb = s * P1STAGE;
        cp16(dA_a + sb, aSrcA + off);            cp16(dA_b + sb, aSrcB + off);
        cp16(dA_a + sb + P1ARR, gSrcA + off);    cp16(dA_b + sb + P1ARR, gSrcB + off);
        cp16(dA_a + sb + 2*P1ARR, uSrcA + off);  cp16(dA_b + sb + 2*P1ARR, uSrcB + off);
        cp_commit();
    }

    #pragma unroll 1
    for (int it = 0; it < DIM / TK; it++) {      // 32 iterations
        cp_wait2();
        __syncthreads();
        if (it + NSTAGE - 1 < DIM / TK) {
            const int off = (it + NSTAGE - 1) * TK;
            const uint32_t sb = ((it + NSTAGE - 1) & 3) * P1STAGE;
            cp16(dA_a + sb, aSrcA + off);            cp16(dA_b + sb, aSrcB + off);
            cp16(dA_a + sb + P1ARR, gSrcA + off);    cp16(dA_b + sb + P1ARR, gSrcB + off);
            cp16(dA_a + sb + 2*P1ARR, uSrcA + off);  cp16(dA_b + sb + 2*P1ARR, uSrcB + off);
        }
        cp_commit();
        const uint32_t* AsP = (const uint32_t*)(ST + (it & 3) * P1STAGE);
        const uint32_t* BgP = (const uint32_t*)(ST + (it & 3) * P1STAGE + P1ARR);
        const uint32_t* BuP = (const uint32_t*)(ST + (it & 3) * P1STAGE + 2 * P1ARR);
        #pragma unroll
        for (int ks = 0; ks < 2; ks++) {
            const int kk = ks * 16;
            uint32_t af[2][4], bg[2][2], bu[2][2];
            #pragma unroll
            for (int mi = 0; mi < 2; mi++) {
                const int r = wm * 32 + mi * 16;
                af[mi][0] = lds_pk(&AsP[(r + g    ) * TSTR + kk + 2 * tg]);
                af[mi][1] = lds_pk(&AsP[(r + g + 8) * TSTR + kk + 2 * tg]);
                af[mi][2] = lds_pk(&AsP[(r + g    ) * TSTR + kk + 8 + 2 * tg]);
                af[mi][3] = lds_pk(&AsP[(r + g + 8) * TSTR + kk + 8 + 2 * tg]);
            }
            #pragma unroll
            for (int ni = 0; ni < 2; ni++) {
                const int c = wn * 16 + ni * 8 + g;
                bg[ni][0] = lds_pk(&BgP[c * TSTR + kk + 2 * tg]);
                bg[ni][1] = lds_pk(&BgP[c * TSTR + kk + 8 + 2 * tg]);
                bu[ni][0] = lds_pk(&BuP[c * TSTR + kk + 2 * tg]);
                bu[ni][1] = lds_pk(&BuP[c * TSTR + kk + 8 + 2 * tg]);
            }
            #pragma unroll
            for (int mi = 0; mi < 2; mi++)
                #pragma unroll
                for (int ni = 0; ni < 2; ni++) {
                    mma_f16(accG[mi][ni], af[mi], bg[ni]);
                    mma_f16(accU[mi][ni], af[mi], bu[ni]);
                }
        }
    }

    // epilogue: h = silu(g)*u -> g_h fp16 (guard partial tiles: owner writes)
    #pragma unroll
    for (int mi = 0; mi < 2; mi++) {
        const int r0 = wm * 32 + mi * 16 + g, r1e = r0 + 8;
        #pragma unroll
        for (int ni = 0; ni < 2; ni++) {
            const int col = nc * 64 + wn * 16 + ni * 8 + 2 * tg;
            if (r0 < rows) {
                float g0 = accG[mi][ni][0], g1 = accG[mi][ni][1];
                float h0 = (g0 / (1.0f + expf(-g0))) * accU[mi][ni][0];
                float h1 = (g1 / (1.0f + expf(-g1))) * accU[mi][ni][1];
                *(uint32_t*)(g_h + (size_t)(row0 + r0) * INTER + col) = pack_f16x2(h0, h1);
            }
            if (r1e < rows) {
                float g2 = accG[mi][ni][2], g3 = accG[mi][ni][3];
                float h2 = (g2 / (1.0f + expf(-g2))) * accU[mi][ni][2];
                float h3 = (g3 / (1.0f + expf(-g3))) * accU[mi][ni][3];
                *(uint32_t*)(g_h + (size_t)(row0 + r1e) * INTER + col) = pack_f16x2(h2, h3);
            }
        }
    }
}

// ---------------------------------------------------------------------------
// K2: out[token[row], nb*128..+128) += w[row] * (h[row] @ W2^T)
// grid (MAXT, 8), 256 threads (2m x 4n warps).
__global__ __launch_bounds__(256, 2)
void gemm2_kernel(const float* __restrict__ w2, const float* __restrict__ w2_s,
                  float* __restrict__ out) {
    const int tile = blockIdx.x;
    if (tile >= g_ntiles) return;
    const TileDesc td = g_tiles[tile];
    const int row0 = td.row0, rows = td.rows;
    const int nb = blockIdx.y, n0 = nb * 128;
    const float* B2 = (td.e < NEXP) ? (w2 + (size_t)td.e * DIM * INTER) : w2_s;

    extern __shared__ char smem[];
    char*  ST   = smem + SM2_ST;
    int*   rtok = (int*)(smem + SM2_RTOK);
    float* rwt  = (float*)(smem + SM2_RWT);

    const int tid = threadIdx.x, lane = tid & 31, warp = tid >> 5;
    const int wm = warp >> 2, wn = warp & 3;
    const int g  = lane >> 2, tg = lane & 3;

    if (tid < TMF) {
        bool v = tid < rows;
        rtok[tid] = v ? g_row_token[row0 + tid] : 0;
        rwt[tid]  = v ? g_row_weight[row0 + tid] : 0.f;
    }
    __syncthreads();

    const uint32_t stBase = (uint32_t)__cvta_generic_to_shared(ST);

    // A (h fp16) loader: 256 16B-units (64 rows x 4), 1 per thread
    const int ra = tid >> 2, ca = (tid & 3) * 8;               // halves
    const __half* aSrc = g_h + (size_t)(row0 + ra) * INTER + ca;
    const uint32_t dAh = stBase + (ra * A2STR + (ca >> 1)) * 4;

    // B (W2 fp32) loader: 1024 units (128 rows x 8), 4 per thread (R7)
    const int r2[4] = { tid >> 3, (tid + 256) >> 3, (tid + 512) >> 3, (tid + 768) >> 3 };
    const int c2[4] = { (tid & 7) * 4, ((tid + 256) & 7) * 4,
                        ((tid + 512) & 7) * 4, ((tid + 768) & 7) * 4 };
    const float* bSrc[4];
    uint32_t dB[4];
    #pragma unroll
    for (int i = 0; i < 4; i++) {
        bSrc[i] = B2 + (size_t)(n0 + r2[i]) * INTER + c2[i];
        dB[i]   = stBase + B2OFF + (r2[i] * TSTR + c2[i]) * 4;
    }

    float acc[2][4][4];
    #pragma unroll
    for (int mi = 0; mi < 2; mi++)
        #pragma unroll
        for (int ni = 0; ni < 4; ni++)
            #pragma unroll
            for (int q = 0; q < 4; q++) acc[mi][ni][q] = 0.f;

    #pragma unroll
    for (int s = 0; s < NSTAGE - 1; s++) {
        const int off = s * TK;
        const uint32_t sb = s * P2STAGE;
        cp16(dAh + sb, aSrc + off);
        #pragma unroll
        for (int i = 0; i < 4; i++) cp16(dB[i] + sb, bSrc[i] + off);
        cp_commit();
    }

    #pragma unroll 1
    for (int it = 0; it < INTER / TK; it++) {    // 16 iterations
        cp_wait2();
        __syncthreads();
        if (it + NSTAGE - 1 < INTER / TK) {
            const int off = (it + NSTAGE - 1) * TK;
            const uint32_t sb = ((it + NSTAGE - 1) & 3) * P2STAGE;
            cp16(dAh + sb, aSrc + off);
            #pragma unroll
            for (int i = 0; i < 4; i++) cp16(dB[i] + sb, bSrc[i] + off);
        }
        cp_commit();
        const uint32_t* AhP = (const uint32_t*)(ST + (it & 3) * P2STAGE);
        const uint32_t* BsP = (const uint32_t*)(ST + (it & 3) * P2STAGE + B2OFF);
        #pragma unroll
        for (int ks = 0; ks < 2; ks++) {
            const int kk  = ks * 16;                 // halves
            const int kkw = ks * 8;                  // u32 words
            uint32_t af[2][4], bf[4][2];
            #pragma unroll
            for (int mi = 0; mi < 2; mi++) {
                const int r = wm * 32 + mi * 16;
                af[mi][0] = AhP[(r + g    ) * A2STR + kkw + tg];
                af[mi][1] = AhP[(r + g + 8) * A2STR + kkw + tg];
                af[mi][2] = AhP[(r + g    ) * A2STR + kkw + 4 + tg];
                af[mi][3] = AhP[(r + g + 8) * A2STR + kkw + 4 + tg];
            }
            #pragma unroll
            for (int ni = 0; ni < 4; ni++) {
                const int c = wn * 32 + ni * 8 + g;
                bf[ni][0] = lds_pk(&BsP[c * TSTR + kk + 2 * tg]);
                bf[ni][1] = lds_pk(&BsP[c * TSTR + kk + 8 + 2 * tg]);
            }
            #pragma unroll
            for (int mi = 0; mi < 2; mi++)
                #pragma unroll
                for (int ni = 0; ni < 4; ni++)
                    mma_f16(acc[mi][ni], af[mi], bf[ni]);
        }
    }

    // epilogue: weighted atomic accumulate into out
    #pragma unroll
    for (int mi = 0; mi < 2; mi++) {
        const int r0 = wm * 32 + mi * 16 + g, r1e = r0 + 8;
        const float w0 = rwt[r0], w1 = rwt[r1e];
        const int   t0 = rtok[r0], t1 = rtok[r1e];
        #pragma unroll
        for (int ni = 0; ni < 4; ni++) {
            const int col = n0 + wn * 32 + ni * 8 + 2 * tg;
            float* q0 = out + (size_t)t0 * DIM + col;
            float* q1 = out + (size_t)t1 * DIM + col;
            atomicAdd(q0 + 0, acc[mi][ni][0] * w0);
            atomicAdd(q0 + 1, acc[mi][ni][1] * w0);
            atomicAdd(q1 + 0, acc[mi][ni][2] * w1);
            atomicAdd(q1 + 1, acc[mi][ni][3] * w1);
        }
    }
}

// ---------------------------------------------------------------------------
namespace {
struct EagerInit {
    EagerInit() {
        cudaFuncAttributes a;
        (void)cudaFuncGetAttributes(&a, (const void*)init_kernel);
        (void)cudaFuncGetAttributes(&a, (const void*)gate_kernel);
        (void)cudaFuncGetAttributes(&a, (const void*)sched_kernel);
        (void)cudaFuncGetAttributes(&a, (const void*)place_kernel);
        (void)cudaFuncGetAttributes(&a, (const void*)gemm1_kernel);
        (void)cudaFuncGetAttributes(&a, (const void*)gemm2_kernel);
        (void)cudaFuncSetAttribute((const void*)gemm1_kernel,
                                   cudaFuncAttributeMaxDynamicSharedMemorySize, SM1_TOTAL);
        (void)cudaFuncSetAttribute((const void*)gemm2_kernel,
                                   cudaFuncAttributeMaxDynamicSharedMemorySize, SM2_TOTAL);
        int zeros[NEXP];
        memset(zeros, 0, sizeof(zeros));
        (void)cudaMemcpyToSymbol(g_counts, zeros, sizeof(zeros));
        init_kernel<<<1, 32>>>();
        (void)cudaDeviceSynchronize();
        (void)cudaGetLastError();
    }
};
static EagerInit eager_init_instance;
}  // namespace

// ---------------------------------------------------------------------------
extern "C" void kernel_launch(void* const* d_in, const int* in_sizes, int n_in,
                              void* d_out, int out_size) {
    const float* x     = (const float*)d_in[0];
    const float* gw    = (const float*)d_in[2];
    const float* gb    = (const float*)d_in[3];
    const float* w13   = (const float*)d_in[4];
    const float* w2    = (const float*)d_in[5];
    const float* w13_s = (const float*)d_in[6];
    const float* w2_s  = (const float*)d_in[7];
    float* out = (float*)d_out;

    (void)cudaFuncSetAttribute((const void*)gemm1_kernel,
                               cudaFuncAttributeMaxDynamicSharedMemorySize, SM1_TOTAL);
    (void)cudaFuncSetAttribute((const void*)gemm2_kernel,
                               cudaFuncAttributeMaxDynamicSharedMemorySize, SM2_TOTAL);

    cudaMemsetAsync(out, 0, (size_t)out_size * sizeof(float), 0);
    init_kernel<<<1, 32>>>();
    gate_kernel<<<T_TOKENS / 8, 256>>>(x, gw, gb);
    sched_kernel<<<1, 1>>>();
    place_kernel<<<NEXP, T_TOKENS>>>();
    gemm1_kernel<<<dim3(MAXT, 8), 256, SM1_TOTAL>>>(x, w13, w13_s);
    gemm2_kernel<<<dim3(MAXT, 8), 256, SM2_TOTAL>>>(w2, w2_s, out);
}

// round 16
// speedup vs baseline: 2.1383x; 1.0406x over previous
#include <cuda_runtime.h>
#include <cuda_fp16.h>
#include <cstdint>
#include <cstring>

// ---------------------------------------------------------------------------
// MoE, two-GEMM split with h in a small fp16 device buffer.
//   K1: per (64-row tile, 64-col chunk): h = silu(x@Wg^T)*(x@Wu^T) -> g_h fp16
//   K2: per (64-row tile, 128-col chunk): y = (h@W2^T)*w -> atomicAdd out
// cp.async fp32 stages + fp16 m16n8k16 consumers. Tiles derived on the fly
// from g_counts (no sched kernel). K1 2 blocks/SM, K2 3 blocks/SM.
// ---------------------------------------------------------------------------

#define T_TOKENS 1024
#define DIM      1024
#define INTER    512
#define NEXP     16
#define TOPK     4
#define NROWS    5120
#define TMF      64
#define MAXT     96
#define TK       32
#define TSTR     36              // fp32 stage row stride (u32): 32 + 4 pad
// K1: depth-4 stages, each A+G+U (64 x TSTR x 4 B per array)
#define P1ARR    9216
#define P1STAGE  27648
// K2: depth-3 stages, each Ah (fp16 64 x 20 u32) + B (fp32 128 x TSTR x 4)
#define A2STR    20
#define B2OFF    5120
#define P2STAGE  23552

__device__ int      g_counts[NEXP];
__device__ int      g_idx[T_TOKENS * TOPK];
__device__ float    g_w[T_TOKENS * TOPK];
__device__ int      g_row_token[NROWS];
__device__ float    g_row_weight[NROWS];
__device__ __half   g_h[(size_t)NROWS * INTER];   // 5.24 MB intermediate

// ---- smem layouts ----------------------------------------------------------
#define SM1_ST    0
#define SM1_RTOK  110592
#define SM1_TOTAL 110848         // 2 blocks/SM

#define SM2_ST    0
#define SM2_RTOK  70656
#define SM2_RWT   70912
#define SM2_TOTAL 71168          // 3 blocks/SM

// ---------------------------------------------------------------------------
__global__ void init_kernel() {
    if (threadIdx.x < NEXP) g_counts[threadIdx.x] = 0;
}

// One warp per token; x row cached in 32 registers (read once).
__global__ __launch_bounds__(256)
void gate_kernel(const float* __restrict__ x, const float* __restrict__ gw,
                 const float* __restrict__ gb) {
    const int token = (blockIdx.x * blockDim.x + threadIdx.x) >> 5;
    const int lane  = threadIdx.x & 31;
    if (token >= T_TOKENS) return;
    const float* xt = x + (size_t)token * DIM;

    float xr[32];
    #pragma unroll
    for (int i = 0; i < 32; i++) xr[i] = xt[lane + 32 * i];

    float myscore = 0.f;
    for (int e = 0; e < NEXP; e++) {
        const float* we = gw + e * DIM;
        float p = 0.f;
        #pragma unroll
        for (int i = 0; i < 32; i++) p += xr[i] * we[lane + 32 * i];
        #pragma unroll
        for (int o = 16; o; o >>= 1) p += __shfl_xor_sync(0xffffffffu, p, o);
        if (lane == e) myscore = 1.0f / (1.0f + expf(-p));
    }
    float mybiased = (lane < NEXP) ? (myscore + gb[lane]) : -1e30f;
    float sum = 0.f; int kidx[TOPK]; float kw[TOPK];
    #pragma unroll
    for (int k = 0; k < TOPK; k++) {
        float v = mybiased; int bl = lane;
        #pragma unroll
        for (int o = 16; o; o >>= 1) {
            float ov = __shfl_xor_sync(0xffffffffu, v, o);
            int   ol = __shfl_xor_sync(0xffffffffu, bl, o);
            if (ov > v || (ov == v && ol < bl)) { v = ov; bl = ol; }
        }
        float sc = __shfl_sync(0xffffffffu, myscore, bl);
        kidx[k] = bl; kw[k] = sc; sum += sc;
        if (lane == bl) mybiased = -1e30f;
    }
    const float s = 2.5f / sum;
    if (lane == 0) {
        #pragma unroll
        for (int k = 0; k < TOPK; k++) {
            g_idx[token * TOPK + k] = kidx[k];
            g_w[token * TOPK + k]   = kw[k] * s;
            atomicAdd(&g_counts[kidx[k]], 1);
        }
        g_row_token[4096 + token]  = token;
        g_row_weight[4096 + token] = 1.0f;
    }
}

// Per-expert compaction; offset computed locally from the 16 counts.
__global__ void place_kernel() {
    __shared__ int s[T_TOKENS];
    __shared__ int off_s;
    const int e = blockIdx.x, t = threadIdx.x;
    if (t == 0) {
        int o = 0;
        for (int i = 0; i < NEXP; i++) if (i < e) o += g_counts[i];
        off_s = o;
    }
    int myk = -1;
    #pragma unroll
    for (int k = 0; k < TOPK; k++)
        if (g_idx[t * TOPK + k] == e) myk = k;
    s[t] = (myk >= 0) ? 1 : 0;
    __syncthreads();
    for (int off = 1; off < T_TOKENS; off <<= 1) {
        int v = (t >= off) ? s[t - off] : 0;
        __syncthreads();
        s[t] += v;
        __syncthreads();
    }
    if (myk >= 0) {
        int row = off_s + s[t] - 1;
        g_row_token[row]  = t;
        g_row_weight[row] = g_w[t * TOPK + myk];
    }
}

// ---------------------------------------------------------------------------
// Derive tile descriptor (expert, row0, rows) for tile index t from g_counts.
__device__ __forceinline__ bool tile_of(int t, int* e, int* row0, int* rows) {
    int off = 0;
    #pragma unroll 1
    for (int i = 0; i < NEXP; i++) {
        const int c  = g_counts[i];
        const int nt = (c + TMF - 1) >> 6;
        if (t < nt) { *e = i; *row0 = off + t * TMF; *rows = min(TMF, c - t * TMF); return true; }
        t -= nt; off += c;
    }
    if (t < T_TOKENS / TMF) { *e = NEXP; *row0 = 4096 + t * TMF; *rows = TMF; return true; }
    return false;
}

__device__ __forceinline__ uint32_t pack_f16x2(float a, float b) {
    uint32_t r;
    asm("cvt.rn.f16x2.f32 %0, %1, %2;" : "=r"(r) : "f"(b), "f"(a));
    return r;
}
__device__ __forceinline__ uint32_t lds_pk(const uint32_t* p) {
    float2 v = *(const float2*)p;
    return pack_f16x2(v.x, v.y);
}
__device__ __forceinline__ void mma_f16(float* d, const uint32_t* a, const uint32_t* b) {
    asm volatile(
        "mma.sync.aligned.m16n8k16.row.col.f32.f16.f16.f32 "
        "{%0,%1,%2,%3},{%4,%5,%6,%7},{%8,%9},{%0,%1,%2,%3};"
        : "+f"(d[0]), "+f"(d[1]), "+f"(d[2]), "+f"(d[3])
        : "r"(a[0]), "r"(a[1]), "r"(a[2]), "r"(a[3]), "r"(b[0]), "r"(b[1]));
}
__device__ __forceinline__ void cp16(uint32_t smem_dst, const void* gsrc) {
    asm volatile("cp.async.ca.shared.global [%0], [%1], 16;\n"
                 :: "r"(smem_dst), "l"(gsrc));
}
__device__ __forceinline__ void cp_commit() {
    asm volatile("cp.async.commit_group;\n");
}
__device__ __forceinline__ void cp_wait2() {
    asm volatile("cp.async.wait_group 2;\n");
}
__device__ __forceinline__ void cp_wait1() {
    asm volatile("cp.async.wait_group 1;\n");
}

// ---------------------------------------------------------------------------
// K1: h[row0..+64)[nc*64..+64) = silu(x@Wg^T)*(x@Wu^T)  (fp16), depth-4.
__global__ __launch_bounds__(256, 2)
void gemm1_kernel(const float* __restrict__ x, const float* __restrict__ w13,
                  const float* __restrict__ w13_s) {
    int e, row0, rows;
    if (!tile_of(blockIdx.x, &e, &row0, &rows)) return;
    const int nc = blockIdx.y;
    const float* B1 = (e < NEXP) ? (w13 + (size_t)e * 1024 * DIM) : w13_s;

    extern __shared__ char smem[];
    char* ST   = smem + SM1_ST;
    int*  rtok = (int*)(smem + SM1_RTOK);

    const int tid = threadIdx.x, lane = tid & 31, warp = tid >> 5;
    const int wm = warp >> 2, wn = warp & 3;
    const int g  = lane >> 2, tg = lane & 3;

    if (tid < TMF)
        rtok[tid] = (tid < rows) ? g_row_token[row0 + tid] : 0;
    __syncthreads();

    const uint32_t stBase = (uint32_t)__cvta_generic_to_shared(ST);
    const int r1a = tid >> 3,         c1a = (tid & 7) * 4;
    const int r1b = (tid + 256) >> 3, c1b = ((tid + 256) & 7) * 4;
    const float* aSrcA = x + (size_t)rtok[r1a] * DIM + c1a;
    const float* aSrcB = x + (size_t)rtok[r1b] * DIM + c1b;
    const uint32_t dA_a = stBase + (r1a * TSTR + c1a) * 4;
    const uint32_t dA_b = stBase + (r1b * TSTR + c1b) * 4;
    const float* gSrcA = B1 + (size_t)(nc * 64 + r1a) * DIM + c1a;
    const float* gSrcB = B1 + (size_t)(nc * 64 + r1b) * DIM + c1b;
    const float* uSrcA = gSrcA + (size_t)512 * DIM;
    const float* uSrcB = gSrcB + (size_t)512 * DIM;

    float accG[2][2][4], accU[2][2][4];
    #pragma unroll
    for (int mi = 0; mi < 2; mi++)
        #pragma unroll
        for (int ni = 0; ni < 2; ni++)
            #pragma unroll
            for (int q = 0; q < 4; q++) { accG[mi][ni][q] = 0.f; accU[mi][ni][q] = 0.f; }

    #pragma unroll
    for (int s = 0; s < 3; s++) {
        const int off = s * TK;
        const uint32_t sb = s * P1STAGE;
        cp16(dA_a + sb, aSrcA + off);            cp16(dA_b + sb, aSrcB + off);
        cp16(dA_a + sb + P1ARR, gSrcA + off);    cp16(dA_b + sb + P1ARR, gSrcB + off);
        cp16(dA_a + sb + 2*P1ARR, uSrcA + off);  cp16(dA_b + sb + 2*P1ARR, uSrcB + off);
        cp_commit();
    }

    #pragma unroll 1
    for (int it = 0; it < DIM / TK; it++) {      // 32 iterations
        cp_wait2();
        __syncthreads();
        if (it + 3 < DIM / TK) {
            const int off = (it + 3) * TK;
            const uint32_t sb = ((it + 3) & 3) * P1STAGE;
            cp16(dA_a + sb, aSrcA + off);            cp16(dA_b + sb, aSrcB + off);
            cp16(dA_a + sb + P1ARR, gSrcA + off);    cp16(dA_b + sb + P1ARR, gSrcB + off);
            cp16(dA_a + sb + 2*P1ARR, uSrcA + off);  cp16(dA_b + sb + 2*P1ARR, uSrcB + off);
        }
        cp_commit();
        const uint32_t* AsP = (const uint32_t*)(ST + (it & 3) * P1STAGE);
        const uint32_t* BgP = (const uint32_t*)(ST + (it & 3) * P1STAGE + P1ARR);
        const uint32_t* BuP = (const uint32_t*)(ST + (it & 3) * P1STAGE + 2 * P1ARR);
        #pragma unroll
        for (int ks = 0; ks < 2; ks++) {
            const int kk = ks * 16;
            uint32_t af[2][4], bg[2][2], bu[2][2];
            #pragma unroll
            for (int mi = 0; mi < 2; mi++) {
                const int r = wm * 32 + mi * 16;
                af[mi][0] = lds_pk(&AsP[(r + g    ) * TSTR + kk + 2 * tg]);
                af[mi][1] = lds_pk(&AsP[(r + g + 8) * TSTR + kk + 2 * tg]);
                af[mi][2] = lds_pk(&AsP[(r + g    ) * TSTR + kk + 8 + 2 * tg]);
                af[mi][3] = lds_pk(&AsP[(r + g + 8) * TSTR + kk + 8 + 2 * tg]);
            }
            #pragma unroll
            for (int ni = 0; ni < 2; ni++) {
                const int c = wn * 16 + ni * 8 + g;
                bg[ni][0] = lds_pk(&BgP[c * TSTR + kk + 2 * tg]);
                bg[ni][1] = lds_pk(&BgP[c * TSTR + kk + 8 + 2 * tg]);
                bu[ni][0] = lds_pk(&BuP[c * TSTR + kk + 2 * tg]);
                bu[ni][1] = lds_pk(&BuP[c * TSTR + kk + 8 + 2 * tg]);
            }
            #pragma unroll
            for (int mi = 0; mi < 2; mi++)
                #pragma unroll
                for (int ni = 0; ni < 2; ni++) {
                    mma_f16(accG[mi][ni], af[mi], bg[ni]);
                    mma_f16(accU[mi][ni], af[mi], bu[ni]);
                }
        }
    }

    #pragma unroll
    for (int mi = 0; mi < 2; mi++) {
        const int r0 = wm * 32 + mi * 16 + g, r1e = r0 + 8;
        #pragma unroll
        for (int ni = 0; ni < 2; ni++) {
            const int col = nc * 64 + wn * 16 + ni * 8 + 2 * tg;
            if (r0 < rows) {
                float g0 = accG[mi][ni][0], g1 = accG[mi][ni][1];
                float h0 = (g0 / (1.0f + expf(-g0))) * accU[mi][ni][0];
                float h1 = (g1 / (1.0f + expf(-g1))) * accU[mi][ni][1];
                *(uint32_t*)(g_h + (size_t)(row0 + r0) * INTER + col) = pack_f16x2(h0, h1);
            }
            if (r1e < rows) {
                float g2 = accG[mi][ni][2], g3 = accG[mi][ni][3];
                float h2 = (g2 / (1.0f + expf(-g2))) * accU[mi][ni][2];
                float h3 = (g3 / (1.0f + expf(-g3))) * accU[mi][ni][3];
                *(uint32_t*)(g_h + (size_t)(row0 + r1e) * INTER + col) = pack_f16x2(h2, h3);
            }
        }
    }
}

// ---------------------------------------------------------------------------
// K2: out[token[row], nb*128..+128) += w[row]*(h[row]@W2^T), depth-3, occ-3.
__global__ __launch_bounds__(256, 3)
void gemm2_kernel(const float* __restrict__ w2, const float* __restrict__ w2_s,
                  float* __restrict__ out) {
    int e, row0, rows;
    if (!tile_of(blockIdx.x, &e, &row0, &rows)) return;
    const int nb = blockIdx.y, n0 = nb * 128;
    const float* B2 = (e < NEXP) ? (w2 + (size_t)e * DIM * INTER) : w2_s;

    extern __shared__ char smem[];
    char*  ST   = smem + SM2_ST;
    int*   rtok = (int*)(smem + SM2_RTOK);
    float* rwt  = (float*)(smem + SM2_RWT);

    const int tid = threadIdx.x, lane = tid & 31, warp = tid >> 5;
    const int wm = warp >> 2, wn = warp & 3;
    const int g  = lane >> 2, tg = lane & 3;

    if (tid < TMF) {
        bool v = tid < rows;
        rtok[tid] = v ? g_row_token[row0 + tid] : 0;
        rwt[tid]  = v ? g_row_weight[row0 + tid] : 0.f;
    }
    __syncthreads();

    const uint32_t stBase = (uint32_t)__cvta_generic_to_shared(ST);
    const int ra = tid >> 2, ca = (tid & 3) * 8;
    const __half* aSrc = g_h + (size_t)(row0 + ra) * INTER + ca;
    const uint32_t dAh = stBase + (ra * A2STR + (ca >> 1)) * 4;

    const int r2[4] = { tid >> 3, (tid + 256) >> 3, (tid + 512) >> 3, (tid + 768) >> 3 };
    const int c2[4] = { (tid & 7) * 4, ((tid + 256) & 7) * 4,
                        ((tid + 512) & 7) * 4, ((tid + 768) & 7) * 4 };
    const float* bSrc[4];
    uint32_t dB[4];
    #pragma unroll
    for (int i = 0; i < 4; i++) {
        bSrc[i] = B2 + (size_t)(n0 + r2[i]) * INTER + c2[i];
        dB[i]   = stBase + B2OFF + (r2[i] * TSTR + c2[i]) * 4;
    }

    float acc[2][4][4];
    #pragma unroll
    for (int mi = 0; mi < 2; mi++)
        #pragma unroll
        for (int ni = 0; ni < 4; ni++)
            #pragma unroll
            for (int q = 0; q < 4; q++) acc[mi][ni][q] = 0.f;

    #pragma unroll
    for (int s = 0; s < 2; s++) {                // depth-3 prologue
        const int off = s * TK;
        const uint32_t sb = s * P2STAGE;
        cp16(dAh + sb, aSrc + off);
        #pragma unroll
        for (int i = 0; i < 4; i++) cp16(dB[i] + sb, bSrc[i] + off);
        cp_commit();
    }

    #pragma unroll 1
    for (int it = 0; it < INTER / TK; it++) {    // 16 iterations
        cp_wait1();
        __syncthreads();
        if (it + 2 < INTER / TK) {
            const int off = (it + 2) * TK;
            const uint32_t sb = (uint32_t)((it + 2) % 3) * P2STAGE;
            cp16(dAh + sb, aSrc + off);
            #pragma unroll
            for (int i = 0; i < 4; i++) cp16(dB[i] + sb, bSrc[i] + off);
        }
        cp_commit();
        const uint32_t* AhP = (const uint32_t*)(ST + (it % 3) * P2STAGE);
        const uint32_t* BsP = (const uint32_t*)(ST + (it % 3) * P2STAGE + B2OFF);
        #pragma unroll
        for (int ks = 0; ks < 2; ks++) {
            const int kk  = ks * 16;
            const int kkw = ks * 8;
            uint32_t af[2][4], bf[4][2];
            #pragma unroll
            for (int mi = 0; mi < 2; mi++) {
                const int r = wm * 32 + mi * 16;
                af[mi][0] = AhP[(r + g    ) * A2STR + kkw + tg];
                af[mi][1] = AhP[(r + g + 8) * A2STR + kkw + tg];
                af[mi][2] = AhP[(r + g    ) * A2STR + kkw + 4 + tg];
                af[mi][3] = AhP[(r + g + 8) * A2STR + kkw + 4 + tg];
            }
            #pragma unroll
            for (int ni = 0; ni < 4; ni++) {
                const int c = wn * 32 + ni * 8 + g;
                bf[ni][0] = lds_pk(&BsP[c * TSTR + kk + 2 * tg]);
                bf[ni][1] = lds_pk(&BsP[c * TSTR + kk + 8 + 2 * tg]);
            }
            #pragma unroll
            for (int mi = 0; mi < 2; mi++)
                #pragma unroll
                for (int ni = 0; ni < 4; ni++)
                    mma_f16(acc[mi][ni], af[mi], bf[ni]);
        }
    }

    #pragma unroll
    for (int mi = 0; mi < 2; mi++) {
        const int r0 = wm * 32 + mi * 16 + g, r1e = r0 + 8;
        const float w0 = rwt[r0], w1 = rwt[r1e];
        const int   t0 = rtok[r0], t1 = rtok[r1e];
        #pragma unroll
        for (int ni = 0; ni < 4; ni++) {
            const int col = n0 + wn * 32 + ni * 8 + 2 * tg;
            float* q0 = out + (size_t)t0 * DIM + col;
            float* q1 = out + (size_t)t1 * DIM + col;
            atomicAdd(q0 + 0, acc[mi][ni][0] * w0);
            atomicAdd(q0 + 1, acc[mi][ni][1] * w0);
            atomicAdd(q1 + 0, acc[mi][ni][2] * w1);
            atomicAdd(q1 + 1, acc[mi][ni][3] * w1);
        }
    }
}

// ---------------------------------------------------------------------------
namespace {
struct EagerInit {
    EagerInit() {
        cudaFuncAttributes a;
        (void)cudaFuncGetAttributes(&a, (const void*)init_kernel);
        (void)cudaFuncGetAttributes(&a, (const void*)gate_kernel);
        (void)cudaFuncGetAttributes(&a, (const void*)place_kernel);
        (void)cudaFuncGetAttributes(&a, (const void*)gemm1_kernel);
        (void)cudaFuncGetAttributes(&a, (const void*)gemm2_kernel);
        (void)cudaFuncSetAttribute((const void*)gemm1_kernel,
                                   cudaFuncAttributeMaxDynamicSharedMemorySize, SM1_TOTAL);
        (void)cudaFuncSetAttribute((const void*)gemm2_kernel,
                                   cudaFuncAttributeMaxDynamicSharedMemorySize, SM2_TOTAL);
        int zeros[NEXP];
        memset(zeros, 0, sizeof(zeros));
        (void)cudaMemcpyToSymbol(g_counts, zeros, sizeof(zeros));
        init_kernel<<<1, 32>>>();
        (void)cudaDeviceSynchronize();
        (void)cudaGetLastError();
    }
};
static EagerInit eager_init_instance;
}  // namespace

// ---------------------------------------------------------------------------
extern "C" void kernel_launch(void* const* d_in, const int* in_sizes, int n_in,
                              void* d_out, int out_size) {
    const float* x     = (const float*)d_in[0];
    const float* gw    = (const float*)d_in[2];
    const float* gb    = (const float*)d_in[3];
    const float* w13   = (const float*)d_in[4];
    const float* w2    = (const float*)d_in[5];
    const float* w13_s = (const float*)d_in[6];
    const float* w2_s  = (const float*)d_in[7];
    float* out = (float*)d_out;

    (void)cudaFuncSetAttribute((const void*)gemm1_kernel,
                               cudaFuncAttributeMaxDynamicSharedMemorySize, SM1_TOTAL);
    (void)cudaFuncSetAttribute((const void*)gemm2_kernel,
                               cudaFuncAttributeMaxDynamicSharedMemorySize, SM2_TOTAL);

    cudaMemsetAsync(out, 0, (size_t)out_size * sizeof(float), 0);
    init_kernel<<<1, 32>>>();
    gate_kernel<<<T_TOKENS / 8, 256>>>(x, gw, gb);
    place_kernel<<<NEXP, T_TOKENS>>>();
    gemm1_kernel<<<dim3(MAXT, 8), 256, SM1_TOTAL>>>(x, w13, w13_s);
    gemm2_kernel<<<dim3(MAXT, 8), 256, SM2_TOTAL>>>(w2, w2_s, out);
}